// round 17
// baseline (speedup 1.0000x reference)
#include <cuda_runtime.h>
#include <cuda_fp16.h>
#include <math.h>

// ---------------- scratch (device globals; no allocation allowed) ----------
#define NTOK 4096            // B*S = 2*2048
#define EMB  1024
#define FFD  4096
#define QKVN 3072

__device__ __half g_ln1h[NTOK * EMB];
__device__ __half g_qkvh[NTOK * QKVN];
__device__ __half g_zh  [NTOK * EMB];
__device__ float  g_h   [NTOK * EMB];
__device__ __half g_ln2h[NTOK * EMB];
__device__ __half g_ffh [NTOK * FFD];
// fp16 TRANSPOSED weights: [N][K] K-major
__device__ __half g_wqkv[QKVN * EMB];
__device__ float  g_bqkv[QKVN];
__device__ __half g_wo  [EMB * EMB];
__device__ __half g_w1t [FFD * EMB];
__device__ __half g_w2t [EMB * FFD];

// ---------------- helpers ---------------------------------------------------
#define CP_ASYNC16(dst_u32, src_ptr) \
    asm volatile("cp.async.cg.shared.global [%0], [%1], 16;" :: "r"(dst_u32), "l"(src_ptr))
#define CP_COMMIT() asm volatile("cp.async.commit_group;")
#define CP_WAIT1()  asm volatile("cp.async.wait_group 1;")
#define CP_WAIT0()  asm volatile("cp.async.wait_group 0;")

#define MMA_F16(d0,d1,d2,d3, a0,a1,a2,a3, b0,b1) \
    asm volatile( \
        "mma.sync.aligned.m16n8k16.row.col.f32.f16.f16.f32 " \
        "{%0,%1,%2,%3}, {%4,%5,%6,%7}, {%8,%9}, {%0,%1,%2,%3};" \
        : "+f"(d0), "+f"(d1), "+f"(d2), "+f"(d3) \
        : "r"(a0), "r"(a1), "r"(a2), "r"(a3), "r"(b0), "r"(b1))

#define LDSM_X4(r0,r1,r2,r3, addr) \
    asm volatile("ldmatrix.sync.aligned.m8n8.x4.shared.b16 {%0,%1,%2,%3}, [%4];" \
        : "=r"(r0), "=r"(r1), "=r"(r2), "=r"(r3) : "r"(addr))

// Per-lane ldmatrix byte offsets for pitch-72-half (144B) tiles.
// A-tile: quad&1 -> row+8, quad&2 -> col+8  => r0..r3 = a0..a3
// B-tile: quad&2 -> row+8, quad&1 -> col+8  => r0,r1 = b[j][0..1], r2,r3 = b[j+1][0..1]
#define LDSM_A_LOFF(lane) (((((lane) >> 3) & 1) * 8 + ((lane) & 7)) * 72 + (((lane) >> 4) & 1) * 8) * 2
#define LDSM_B_LOFF(lane) (((((lane) >> 4) & 1) * 8 + ((lane) & 7)) * 72 + (((lane) >> 3) & 1) * 8) * 2

// ---------------- fused weight prep: all 6 transposes in one launch ---------
__global__ void __launch_bounds__(256) prep_weights_kernel(
    const float* __restrict__ Wq, const float* __restrict__ Wk,
    const float* __restrict__ Wv, const float* __restrict__ Wo,
    const float* __restrict__ W1, const float* __restrict__ W2,
    __half* __restrict__ wqkv, __half* __restrict__ wo,
    __half* __restrict__ w1t, __half* __restrict__ w2t)
{
    int bid = blockIdx.x;
    const float* src; __half* dst; int K, N, ti;
    if (bid < 1024)      { src = Wq; dst = wqkv;               K = EMB; N = EMB; ti = bid; }
    else if (bid < 2048) { src = Wk; dst = wqkv + EMB * EMB;   K = EMB; N = EMB; ti = bid - 1024; }
    else if (bid < 3072) { src = Wv; dst = wqkv + 2*EMB*EMB;   K = EMB; N = EMB; ti = bid - 2048; }
    else if (bid < 4096) { src = Wo; dst = wo;                 K = EMB; N = EMB; ti = bid - 3072; }
    else if (bid < 8192) { src = W1; dst = w1t;                K = EMB; N = FFD; ti = bid - 4096; }
    else                 { src = W2; dst = w2t;                K = FFD; N = EMB; ti = bid - 8192; }
    int nx = N / 32;
    int n0 = (ti % nx) * 32, k0 = (ti / nx) * 32;

    __shared__ float tile[32][33];
    int tx = threadIdx.x & 31, ty = threadIdx.x >> 5;
    #pragma unroll
    for (int i = 0; i < 32; i += 8)
        tile[ty + i][tx] = src[(size_t)(k0 + ty + i) * N + n0 + tx];
    __syncthreads();
    #pragma unroll
    for (int i = 0; i < 32; i += 8)
        dst[(size_t)(n0 + ty + i) * K + k0 + tx] = __float2half_rn(tile[tx][ty + i]);
}

__global__ void __launch_bounds__(256) pack_qkv_b_kernel(
    const float* __restrict__ bq, const float* __restrict__ bk,
    const float* __restrict__ bv, float* __restrict__ out)
{
    int i = blockIdx.x * blockDim.x + threadIdx.x;
    if (i >= QKVN) return;
    out[i] = (i < EMB) ? bq[i] : (i < 2 * EMB) ? bk[i - EMB] : bv[i - 2 * EMB];
}

// ---------------- LayerNorm (fp16 output: feeds GEMMs) ----------------------
__global__ void __launch_bounds__(256) layernorm_kernel(
    const float* __restrict__ x, const float* __restrict__ g,
    const float* __restrict__ b, __half* __restrict__ out)
{
    int row = blockIdx.x;
    int tid = threadIdx.x;
    const float4* xr = (const float4*)(x + (size_t)row * EMB);
    float4 v = xr[tid];
    float s  = v.x + v.y + v.z + v.w;
    float ss = v.x*v.x + v.y*v.y + v.z*v.z + v.w*v.w;
    #pragma unroll
    for (int off = 16; off > 0; off >>= 1) {
        s  += __shfl_xor_sync(0xffffffffu, s,  off);
        ss += __shfl_xor_sync(0xffffffffu, ss, off);
    }
    __shared__ float sbuf[8], ssbuf[8], red[2];
    int warp = tid >> 5, lane = tid & 31;
    if (lane == 0) { sbuf[warp] = s; ssbuf[warp] = ss; }
    __syncthreads();
    if (tid < 32) {
        float a = (tid < 8) ? sbuf[tid]  : 0.f;
        float c = (tid < 8) ? ssbuf[tid] : 0.f;
        #pragma unroll
        for (int off = 4; off > 0; off >>= 1) {
            a += __shfl_xor_sync(0xffffffffu, a, off);
            c += __shfl_xor_sync(0xffffffffu, c, off);
        }
        if (tid == 0) { red[0] = a; red[1] = c; }
    }
    __syncthreads();
    float mu   = red[0] * (1.0f / EMB);
    float var  = red[1] * (1.0f / EMB) - mu * mu;
    float rstd = rsqrtf(var + 1e-5f);
    float4 gg = ((const float4*)g)[tid];
    float4 bb = ((const float4*)b)[tid];
    __half2 p0 = __floats2half2_rn((v.x - mu) * rstd * gg.x + bb.x,
                                   (v.y - mu) * rstd * gg.y + bb.y);
    __half2 p1 = __floats2half2_rn((v.z - mu) * rstd * gg.z + bb.z,
                                   (v.w - mu) * rstd * gg.w + bb.w);
    uint2 pk;
    pk.x = *(unsigned*)&p0; pk.y = *(unsigned*)&p1;
    ((uint2*)(out + (size_t)row * EMB))[tid] = pk;
}

// ---------------- FP16 GEMM: 128x256x64 tile, warp tile 64x64, LDSM ---------
// 256 threads / 8 warps (2M x 4N), 1 CTA/SM, 3-stage cp.async, ONE barrier/iter.
#define APH 72
#define A_STG_H (128 * APH)                    // A halves per stage
#define B_STG_H (256 * APH)                    // B halves per stage
#define STG_H   (A_STG_H + B_STG_H)
#define STG_BYTES (STG_H * 2)                  // 55296
#define NSTAGE 3
#define GEMM_SMEM (NSTAGE * STG_BYTES)

#define GEMM_ISSUE(k0, buf) do {                                                \
    _Pragma("unroll")                                                           \
    for (int l = 0; l < 4; l++) {                                               \
        int idx = tid + l * 256;                                                \
        int r = idx >> 3, c = idx & 7;                                          \
        const __half* src = A + (size_t)(m0 + r) * K + (k0) + c * 8;            \
        CP_ASYNC16(as_base + (unsigned)((buf) * STG_BYTES + r * 144 + c * 16), src); \
    }                                                                           \
    _Pragma("unroll")                                                           \
    for (int l = 0; l < 8; l++) {                                               \
        int idx = tid + l * 256;                                                \
        int r = idx >> 3, c = idx & 7;                                          \
        const __half* src = Wt + (size_t)(n0 + r) * K + (k0) + c * 8;           \
        CP_ASYNC16(bs_base + (unsigned)((buf) * STG_BYTES + r * 144 + c * 16), src); \
    }                                                                           \
    CP_COMMIT();                                                                \
} while (0)

template<bool BIAS, bool GELU, bool RES, bool OUTH>
__global__ void __launch_bounds__(256) gemm_f16_kernel(
    const __half* __restrict__ A, const __half* __restrict__ Wt,
    const float* __restrict__ bias, const float* __restrict__ res,
    void* __restrict__ Cv, int M, int N, int K)
{
    extern __shared__ __half smh[];
    __half* As = smh;                     // per stage: [128][APH]
    __half* Bs = smh + A_STG_H;           // per stage: [256][APH]

    const int tid  = threadIdx.x;
    const int lane = tid & 31;
    const int warp = tid >> 5;
    const int wm   = warp >> 2;           // 0..1 : 64 M-rows
    const int wn   = warp & 3;            // 0..3 : 64 N-cols
    const int g    = lane >> 2;
    const int t4   = lane & 3;
    const int m0 = blockIdx.y * 128, n0 = blockIdx.x * 256;

    unsigned as_base = (unsigned)__cvta_generic_to_shared(As);
    unsigned bs_base = (unsigned)__cvta_generic_to_shared(Bs);
    const unsigned a_loff = LDSM_A_LOFF(lane);
    const unsigned b_loff = LDSM_B_LOFF(lane);

    float acc[4][8][4];
    #pragma unroll
    for (int i = 0; i < 4; i++)
        #pragma unroll
        for (int j = 0; j < 8; j++)
            #pragma unroll
            for (int q = 0; q < 4; q++) acc[i][j][q] = 0.f;

    const int T = K / 64;
    GEMM_ISSUE(0, 0);
    GEMM_ISSUE(64, 1);

    int rd = 0, wr = 2;
    for (int it = 0; it < T; it++) {
        if (it + 1 < T) CP_WAIT1(); else CP_WAIT0();
        __syncthreads();                       // orders prev-iter reads before refill
        if (it + 2 < T) {
            GEMM_ISSUE((it + 2) * 64, wr);
            wr = (wr == 2) ? 0 : wr + 1;
        }

        const unsigned asb = as_base + rd * STG_BYTES;
        const unsigned bsb = bs_base + rd * STG_BYTES;
        rd = (rd == 2) ? 0 : rd + 1;

        #pragma unroll
        for (int ks = 0; ks < 4; ks++) {
            const int kb = ks * 16;
            unsigned a[4][4], b[8][2];
            #pragma unroll
            for (int im = 0; im < 4; im++)
                LDSM_X4(a[im][0], a[im][1], a[im][2], a[im][3],
                        asb + (unsigned)(((wm * 64 + im * 16) * APH + kb) * 2) + a_loff);
            #pragma unroll
            for (int j2 = 0; j2 < 4; j2++)
                LDSM_X4(b[2*j2][0], b[2*j2][1], b[2*j2+1][0], b[2*j2+1][1],
                        bsb + (unsigned)(((wn * 64 + j2 * 16) * APH + kb) * 2) + b_loff);
            #pragma unroll
            for (int jn = 0; jn < 8; jn++)
                #pragma unroll
                for (int im = 0; im < 4; im++)
                    MMA_F16(acc[im][jn][0], acc[im][jn][1], acc[im][jn][2], acc[im][jn][3],
                            a[im][0], a[im][1], a[im][2], a[im][3],
                            b[jn][0], b[jn][1]);
        }
    }

    // ---- epilogue ----
    #pragma unroll
    for (int im = 0; im < 4; im++) {
        int r0 = m0 + wm * 64 + im * 16 + g;
        #pragma unroll
        for (int jn = 0; jn < 8; jn++) {
            int c = n0 + wn * 64 + jn * 8 + t4 * 2;
            float v[4] = { acc[im][jn][0], acc[im][jn][1],
                           acc[im][jn][2], acc[im][jn][3] };
            if (BIAS) {
                float2 bq = *(const float2*)(bias + c);
                v[0] += bq.x; v[1] += bq.y; v[2] += bq.x; v[3] += bq.y;
            }
            if (GELU) {
                #pragma unroll
                for (int q = 0; q < 4; q++)
                    v[q] = 0.5f * v[q] * (1.0f + erff(v[q] * 0.70710678118654752f));
            }
            if (RES) {
                float2 rlo = *(const float2*)(res + (size_t)r0 * N + c);
                float2 rhi = *(const float2*)(res + (size_t)(r0 + 8) * N + c);
                v[0] += rlo.x; v[1] += rlo.y; v[2] += rhi.x; v[3] += rhi.y;
            }
            if (OUTH) {
                __half* C = (__half*)Cv;
                *(__half2*)(C + (size_t)r0 * N + c)       = __floats2half2_rn(v[0], v[1]);
                *(__half2*)(C + (size_t)(r0 + 8) * N + c) = __floats2half2_rn(v[2], v[3]);
            } else {
                float* C = (float*)Cv;
                float2 lo; lo.x = v[0]; lo.y = v[1];
                float2 hi; hi.x = v[2]; hi.y = v[3];
                *(float2*)(C + (size_t)r0 * N + c)       = lo;
                *(float2*)(C + (size_t)(r0 + 8) * N + c) = hi;
            }
        }
    }
}

// ---------------- Flash attention: fp16 mma + LDSM, BQ=128, ONE sync/iter ---
#define FP 72
#define FLASH_SMEM ((128 + 2 * 64 + 2 * 64 + 128) * FP * 2)

#define FLASH_K_ISSUE(kvbase, buf) do {                                         \
    _Pragma("unroll")                                                           \
    for (int l = 0; l < 2; l++) {                                               \
        int idx = tid + l * 256;                                                \
        int r = idx >> 3, c = idx & 7;                                          \
        const __half* src = QKV + base_k + (size_t)((kvbase) + r) * QKVN + c * 8; \
        CP_ASYNC16(ks_base + (unsigned)((buf) * 64 * 144 + r * 144 + c * 16), src); \
    }                                                                           \
    CP_COMMIT();                                                                \
} while (0)

__global__ void __launch_bounds__(256) flash_f16_kernel(
    const __half* __restrict__ QKV, __half* __restrict__ O)
{
    extern __shared__ __half smf[];
    __half* Qs  = smf;                    // [128][FP]
    __half* Ks  = Qs  + 128 * FP;         // [2][64][FP]
    __half* Vts = Ks  + 2 * 64 * FP;      // [2][64][FP]  V^T: [d][kv]
    __half* Ps  = Vts + 2 * 64 * FP;      // [128][FP]

    const int tid  = threadIdx.x;
    const int lane = tid & 31;
    const int warp = tid >> 5;            // 0..7
    const int g    = lane >> 2;
    const int t4   = lane & 3;

    const int bh = blockIdx.y;
    const int b = bh >> 4, h = bh & 15;
    const int qb = (int)gridDim.x - 1 - (int)blockIdx.x;   // heavy blocks first
    const int qbase = qb * 128;
    const size_t base_q = ((size_t)b * 2048) * QKVN + h * 64;
    const size_t base_k = base_q + EMB;
    const size_t base_v = base_q + 2 * EMB;
    const size_t base_o = ((size_t)b * 2048) * EMB + h * 64;

    unsigned qs_base  = (unsigned)__cvta_generic_to_shared(Qs);
    unsigned ks_base  = (unsigned)__cvta_generic_to_shared(Ks);
    unsigned vts_base = (unsigned)__cvta_generic_to_shared(Vts);
    unsigned ps_base  = (unsigned)__cvta_generic_to_shared(Ps);
    const unsigned a_loff = LDSM_A_LOFF(lane);
    const unsigned b_loff = LDSM_B_LOFF(lane);

    // prologue: Q (128 rows) + K tile 0 (one cp.async group)
    #pragma unroll
    for (int l = 0; l < 4; l++) {
        int idx = tid + l * 256;
        int r = idx >> 3, c = idx & 7;
        const __half* src = QKV + base_q + (size_t)(qbase + r) * QKVN + c * 8;
        CP_ASYNC16(qs_base + (unsigned)(r * 144 + c * 16), src);
    }
    {
        #pragma unroll
        for (int l = 0; l < 2; l++) {
            int idx = tid + l * 256;
            int r = idx >> 3, c = idx & 7;
            const __half* src = QKV + base_k + (size_t)r * QKVN + c * 8;
            CP_ASYNC16(ks_base + (unsigned)(r * 144 + c * 16), src);
        }
        CP_COMMIT();
    }

    // V tile 0 -> Vt buffer 0. Thread owns kv row tid>>2, d-range (tid&3)*16..+15
    const int vrow = tid >> 2;
    const int vd0  = (tid & 3) * 16;
    __half2 vreg[8];
    #pragma unroll
    for (int j = 0; j < 8; j++)
        vreg[j] = *(const __half2*)(QKV + base_v + (size_t)vrow * QKVN + vd0 + 2 * j);
    #pragma unroll
    for (int j = 0; j < 8; j++) {
        Vts[(vd0 + 2 * j    ) * FP + vrow] = __low2half(vreg[j]);
        Vts[(vd0 + 2 * j + 1) * FP + vrow] = __high2half(vreg[j]);
    }

    float m0 = -1e30f, m1 = -1e30f, l0 = 0.f, l1 = 0.f;
    float acc[8][4];
    #pragma unroll
    for (int n = 0; n < 8; n++)
        #pragma unroll
        for (int q = 0; q < 4; q++) acc[n][q] = 0.f;

    const int row0l = warp * 16 + g;
    const int grow0 = qbase + row0l;
    const int grow1 = grow0 + 8;
    const float scale = 0.03125f;       // 1/sqrt(1024)
    const int tmax = 2 * qb + 1;

    for (int t = 0; t <= tmax; t++) {
        const int kvbase = t * 64;
        CP_WAIT0();                        // K(t) group complete
        __syncthreads();                   // all warps done with iter t-1 buffers

        if (t < tmax) {
            FLASH_K_ISSUE(kvbase + 64, (t + 1) & 1);   // safe: buffer last read in t-1
            #pragma unroll
            for (int j = 0; j < 8; j++)                 // V(t+1) prefetch
                vreg[j] = *(const __half2*)(QKV + base_v +
                    (size_t)(kvbase + 64 + vrow) * QKVN + vd0 + 2 * j);
        }

        const unsigned ksb = ks_base + (t & 1) * 64 * 144;
        const unsigned vsb = vts_base + (t & 1) * 64 * 144;

        // ---- S = Q @ K^T ----
        float s[8][4];
        #pragma unroll
        for (int n = 0; n < 8; n++)
            #pragma unroll
            for (int q = 0; q < 4; q++) s[n][q] = 0.f;

        #pragma unroll
        for (int ks = 0; ks < 4; ks++) {
            const int kb = ks * 16;
            unsigned a[4], bfr[8][2];
            LDSM_X4(a[0], a[1], a[2], a[3],
                    qs_base + (unsigned)(((warp * 16) * FP + kb) * 2) + a_loff);
            #pragma unroll
            for (int j2 = 0; j2 < 4; j2++)
                LDSM_X4(bfr[2*j2][0], bfr[2*j2][1], bfr[2*j2+1][0], bfr[2*j2+1][1],
                        ksb + (unsigned)(((j2 * 16) * FP + kb) * 2) + b_loff);
            #pragma unroll
            for (int n = 0; n < 8; n++)
                MMA_F16(s[n][0], s[n][1], s[n][2], s[n][3],
                        a[0], a[1], a[2], a[3], bfr[n][0], bfr[n][1]);
        }

        // ---- scale + causal mask ----
        const bool diag = (kvbase + 63 > qbase);
        #pragma unroll
        for (int n = 0; n < 8; n++) {
            int c0 = kvbase + n * 8 + 2 * t4;
            s[n][0] *= scale; s[n][1] *= scale;
            s[n][2] *= scale; s[n][3] *= scale;
            if (diag) {
                if (c0     > grow0) s[n][0] = -1e30f;
                if (c0 + 1 > grow0) s[n][1] = -1e30f;
                if (c0     > grow1) s[n][2] = -1e30f;
                if (c0 + 1 > grow1) s[n][3] = -1e30f;
            }
        }

        // ---- online softmax (fp32) ----
        float mx0 = -1e30f, mx1 = -1e30f;
        #pragma unroll
        for (int n = 0; n < 8; n++) {
            mx0 = fmaxf(mx0, fmaxf(s[n][0], s[n][1]));
            mx1 = fmaxf(mx1, fmaxf(s[n][2], s[n][3]));
        }
        mx0 = fmaxf(mx0, __shfl_xor_sync(0xffffffffu, mx0, 1));
        mx0 = fmaxf(mx0, __shfl_xor_sync(0xffffffffu, mx0, 2));
        mx1 = fmaxf(mx1, __shfl_xor_sync(0xffffffffu, mx1, 1));
        mx1 = fmaxf(mx1, __shfl_xor_sync(0xffffffffu, mx1, 2));

        float mn0 = fmaxf(m0, mx0), mn1 = fmaxf(m1, mx1);
        float al0 = __expf(m0 - mn0), al1 = __expf(m1 - mn1);
        m0 = mn0; m1 = mn1;

        float rs0 = 0.f, rs1 = 0.f;
        #pragma unroll
        for (int n = 0; n < 8; n++) {
            s[n][0] = __expf(s[n][0] - mn0);
            s[n][1] = __expf(s[n][1] - mn0);
            s[n][2] = __expf(s[n][2] - mn1);
            s[n][3] = __expf(s[n][3] - mn1);
            rs0 += s[n][0] + s[n][1];
            rs1 += s[n][2] + s[n][3];
        }
        rs0 += __shfl_xor_sync(0xffffffffu, rs0, 1);
        rs0 += __shfl_xor_sync(0xffffffffu, rs0, 2);
        rs1 += __shfl_xor_sync(0xffffffffu, rs1, 1);
        rs1 += __shfl_xor_sync(0xffffffffu, rs1, 2);
        l0 = l0 * al0 + rs0;
        l1 = l1 * al1 + rs1;

        #pragma unroll
        for (int n = 0; n < 8; n++) {
            acc[n][0] *= al0; acc[n][1] *= al0;
            acc[n][2] *= al1; acc[n][3] *= al1;
            *(__half2*)&Ps[(row0l    ) * FP + n * 8 + 2 * t4] =
                __floats2half2_rn(s[n][0], s[n][1]);
            *(__half2*)&Ps[(row0l + 8) * FP + n * 8 + 2 * t4] =
                __floats2half2_rn(s[n][2], s[n][3]);
        }
        __syncwarp();   // each warp reads only its own P rows

        // ---- acc += P @ V  (B = Vt[t&1]) ----
        #pragma unroll
        for (int ks = 0; ks < 4; ks++) {
            const int kb = ks * 16;
            unsigned a[4], bfr[8][2];
            LDSM_X4(a[0], a[1], a[2], a[3],
                    ps_base + (unsigned)(((warp * 16) * FP + kb) * 2) + a_loff);
            #pragma unroll
            for (int j2 = 0; j2 < 4; j2++)
                LDSM_X4(bfr[2*j2][0], bfr[2*j2][1], bfr[2*j2+1][0], bfr[2*j2+1][1],
                        vsb + (unsigned)(((j2 * 16) * FP + kb) * 2) + b_loff);
            #pragma unroll
            for (int n = 0; n < 8; n++)
                MMA_F16(acc[n][0], acc[n][1], acc[n][2], acc[n][3],
                        a[0], a[1], a[2], a[3], bfr[n][0], bfr[n][1]);
        }

        // store V(t+1) into the other Vt buffer — its last readers finished
        // before the top-of-iteration sync of this iteration.
        if (t < tmax) {
            __half* vdst = Vts + ((t + 1) & 1) * 64 * FP;
            #pragma unroll
            for (int j = 0; j < 8; j++) {
                vdst[(vd0 + 2 * j    ) * FP + vrow] = __low2half(vreg[j]);
                vdst[(vd0 + 2 * j + 1) * FP + vrow] = __high2half(vreg[j]);
            }
        }
    }

    // ---- write O = acc / l as fp16 ----
    float inv0 = 1.0f / l0, inv1 = 1.0f / l1;
    #pragma unroll
    for (int n = 0; n < 8; n++) {
        int c = n * 8 + 2 * t4;
        *(__half2*)(O + base_o + (size_t)grow0 * EMB + c) =
            __floats2half2_rn(acc[n][0] * inv0, acc[n][1] * inv0);
        *(__half2*)(O + base_o + (size_t)grow1 * EMB + c) =
            __floats2half2_rn(acc[n][2] * inv1, acc[n][3] * inv1);
    }
}

// ---------------- launch ----------------------------------------------------
extern "C" void kernel_launch(void* const* d_in, const int* in_sizes, int n_in,
                              void* d_out, int out_size)
{
    const float* x   = (const float*)d_in[0];
    const float* Wq  = (const float*)d_in[1];
    const float* bq  = (const float*)d_in[2];
    const float* Wk  = (const float*)d_in[3];
    const float* bk  = (const float*)d_in[4];
    const float* Wv  = (const float*)d_in[5];
    const float* bv  = (const float*)d_in[6];
    const float* Wo  = (const float*)d_in[7];
    const float* W1  = (const float*)d_in[8];
    const float* b1  = (const float*)d_in[9];
    const float* W2  = (const float*)d_in[10];
    const float* b2  = (const float*)d_in[11];
    const float* g1  = (const float*)d_in[12];
    const float* be1 = (const float*)d_in[13];
    const float* g2  = (const float*)d_in[14];
    const float* be2 = (const float*)d_in[15];
    float* out = (float*)d_out;

    __half *ln1h, *qkvh, *zh, *ln2h, *ffh, *wqkv, *wo, *w1t, *w2t;
    float *hb, *bqkv;
    cudaGetSymbolAddress((void**)&ln1h, g_ln1h);
    cudaGetSymbolAddress((void**)&qkvh, g_qkvh);
    cudaGetSymbolAddress((void**)&zh,   g_zh);
    cudaGetSymbolAddress((void**)&hb,   g_h);
    cudaGetSymbolAddress((void**)&ln2h, g_ln2h);
    cudaGetSymbolAddress((void**)&ffh,  g_ffh);
    cudaGetSymbolAddress((void**)&wqkv, g_wqkv);
    cudaGetSymbolAddress((void**)&bqkv, g_bqkv);
    cudaGetSymbolAddress((void**)&wo,   g_wo);
    cudaGetSymbolAddress((void**)&w1t,  g_w1t);
    cudaGetSymbolAddress((void**)&w2t,  g_w2t);

    cudaFuncSetAttribute(gemm_f16_kernel<true,  false, false, true >,
                         cudaFuncAttributeMaxDynamicSharedMemorySize, GEMM_SMEM);
    cudaFuncSetAttribute(gemm_f16_kernel<false, false, true,  false>,
                         cudaFuncAttributeMaxDynamicSharedMemorySize, GEMM_SMEM);
    cudaFuncSetAttribute(gemm_f16_kernel<true,  true,  false, true >,
                         cudaFuncAttributeMaxDynamicSharedMemorySize, GEMM_SMEM);
    cudaFuncSetAttribute(gemm_f16_kernel<true,  false, true,  false>,
                         cudaFuncAttributeMaxDynamicSharedMemorySize, GEMM_SMEM);
    cudaFuncSetAttribute(flash_f16_kernel,
                         cudaFuncAttributeMaxDynamicSharedMemorySize, FLASH_SMEM);

    // 0) weight prep (single fused launch + bias pack)
    prep_weights_kernel<<<12288, 256>>>(Wq, Wk, Wv, Wo, W1, W2, wqkv, wo, w1t, w2t);
    pack_qkv_b_kernel<<<(QKVN + 255) / 256, 256>>>(bq, bk, bv, bqkv);

    // 1) ln1 = fp16(LN(x))
    layernorm_kernel<<<NTOK, 256>>>(x, g1, be1, ln1h);

    // 2) fused QKV projection (fp16 mma), fp16 output
    gemm_f16_kernel<true, false, false, true><<<dim3(QKVN / 256, NTOK / 128), 256, GEMM_SMEM>>>(
        ln1h, wqkv, bqkv, nullptr, qkvh, NTOK, QKVN, EMB);

    // 3) causal flash attention (fp16 mma, fp32 softmax), BQ=128
    flash_f16_kernel<<<dim3(16, 32), 256, FLASH_SMEM>>>(qkvh, zh);

    // 4) h = x + z @ Wo  (fp32 output)
    gemm_f16_kernel<false, false, true, false><<<dim3(EMB / 256, NTOK / 128), 256, GEMM_SMEM>>>(
        zh, wo, nullptr, x, hb, NTOK, EMB, EMB);

    // 5) ln2 = fp16(LN(h))
    layernorm_kernel<<<NTOK, 256>>>(hb, g2, be2, ln2h);

    // 6) ff = fp16(gelu(ln2 @ W1 + b1))
    gemm_f16_kernel<true, true, false, true><<<dim3(FFD / 256, NTOK / 128), 256, GEMM_SMEM>>>(
        ln2h, w1t, b1, nullptr, ffh, NTOK, FFD, EMB);

    // 7) out = h + ff @ W2 + b2  (fp32 output)
    gemm_f16_kernel<true, false, true, false><<<dim3(EMB / 256, NTOK / 128), 256, GEMM_SMEM>>>(
        ffh, w2t, b2, hb, out, NTOK, EMB, FFD);
}